// round 14
// baseline (speedup 1.0000x reference)
#include <cuda_runtime.h>
#include <cuda_bf16.h>
#include <cmath>

#define N_NODES 20000
#define N_EDGES 320000
#define MAXD    1024
#define N_OUT   1024      // layer-4 rows consumed by the readout (order+1)

// GEMM tiling constants
#define GBM 128
#define GBN 128
#define GBK 16
#define A_TILE_F 2304     // 64 lane-slots * 36 floats
#define B_TILE_F 2560     // 128 lane-slots * 20 floats
#define GEMM_SMEM (3 * (A_TILE_F + B_TILE_F) * 4)   // 58368 bytes

// K1 block ranges: count | wv | wperm(slot-per-thread)
#define CNT_B    1250
#define WV_B     120
#define WPERM_B  170      // 43520 slots / 256
#define K1_B     (CNT_B + WV_B + WPERM_B)
// K3 block ranges: fill | elr
#define FILL_B   1250
#define ELR_B    2500
#define K3_B     (FILL_B + ELR_B)

// ---------------- scratch (static __device__, zero-init, no allocs) ----------------
__device__ float g_bufA[(size_t)N_NODES * MAXD];
__device__ float g_bufB[(size_t)N_NODES * MAXD];
__device__ float g_Z  [(size_t)157 * 32 * A_TILE_F];          // permuted GEMM-A
__device__ float g_Wp [(size_t)340 * B_TILE_F];               // permuted GEMM-B, 4 layers
__device__ float g_el[2][N_NODES];                            // ping-pong el/er
__device__ float g_er[2][N_NODES];
__device__ float g_wal[4][512];
__device__ float g_war[4][512];
__device__ int   g_rowptr[N_NODES + 1];
__device__ int   g_cnt[N_NODES];      // invariant: == 0 at kernel_launch entry
__device__ int   g_fill[N_NODES];     // fill cursor, seeded by scan
__device__ int   g_csrc[N_EDGES];
__device__ float g_poolpart[32 * MAXD];

__device__ __forceinline__ unsigned f2tf32(float f) {
    unsigned u;
    asm("cvt.rna.tf32.f32 %0, %1;" : "=r"(u) : "f"(f));
    return u;
}

__constant__ int c_din[4]   = {64, 128, 256, 512};
__constant__ int c_dout[4]  = {128, 256, 512, 1024};
__constant__ int c_wpoff[4] = {0, 4, 20, 84};
__constant__ int c_l2ntn[4] = {0, 1, 2, 3};

// ---------------- K1: count (g_cnt starts zeroed) + wv + wperm ----------------
__global__ __launch_bounds__(256) void k1_kernel(
    const int* __restrict__ dst,
    const float* __restrict__ W0, const float* __restrict__ W1,
    const float* __restrict__ W2, const float* __restrict__ W3,
    const float* __restrict__ al0, const float* __restrict__ al1,
    const float* __restrict__ al2, const float* __restrict__ al3,
    const float* __restrict__ ar0, const float* __restrict__ ar1,
    const float* __restrict__ ar2, const float* __restrict__ ar3)
{
    const float* Ws[4]  = {W0, W1, W2, W3};
    const float* als[4] = {al0, al1, al2, al3};
    const float* ars[4] = {ar0, ar1, ar2, ar3};
    int bid = blockIdx.x;

    if (bid < CNT_B) {
        int e = bid * 256 + threadIdx.x;
        if (e < N_EDGES) atomicAdd(&g_cnt[dst[e]], 1);
        return;
    }
    bid -= CNT_B;
    if (bid < WV_B) {
        int l, b0;
        if      (bid < 8)  { l = 0; b0 = 0; }
        else if (bid < 24) { l = 1; b0 = 8; }
        else if (bid < 56) { l = 2; b0 = 24; }
        else               { l = 3; b0 = 56; }
        int din = c_din[l], dout = c_dout[l];
        int wid = (bid - b0) * 8 + (threadIdx.x >> 5);
        int lane = threadIdx.x & 31;
        if (wid >= din) return;
        const float* row = Ws[l] + (size_t)wid * dout;
        const float* al = als[l];
        const float* ar = ars[l];
        float sl = 0.f, sr = 0.f;
        for (int j = lane; j < dout; j += 32) {
            float w = row[j];
            sl += w * al[j];
            sr += w * ar[j];
        }
#pragma unroll
        for (int o = 16; o > 0; o >>= 1) {
            sl += __shfl_down_sync(0xffffffffu, sl, o);
            sr += __shfl_down_sync(0xffffffffu, sr, o);
        }
        if (lane == 0) { g_wal[l][wid] = sl; g_war[l][wid] = sr; }
        return;
    }
    bid -= WV_B;
    {
        // wperm: one lane-slot (16 tf32 values) per thread, coalesced-ish float4 stores
        int sid = bid * 256 + threadIdx.x;   // 0..43519
        int l, base;
        if      (sid < 512)   { l = 0; base = 0; }
        else if (sid < 2560)  { l = 1; base = 512; }
        else if (sid < 10752) { l = 2; base = 2560; }
        else                  { l = 3; base = 10752; }
        int dout = c_dout[l];
        int ntn = dout >> 7;
        int sp = sid - base;
        int slot = sp & 127;
        int tile = sp >> 7;
        int nt = tile & (ntn - 1);
        int kt = tile >> c_l2ntn[l];
        int wn = slot >> 5, g = (slot >> 2) & 7, t = slot & 3;
        const float* Wl = Ws[l];
        __align__(16) float f[16];
#pragma unroll
        for (int ks = 0; ks < 2; ks++)
#pragma unroll
            for (int kh = 0; kh < 2; kh++) {
                int k = kt * 16 + ks * 8 + kh * 4 + t;
                const float* wr = Wl + (size_t)k * dout + nt * 128 + wn * 32 + g;
#pragma unroll
                for (int ni = 0; ni < 4; ni++)
                    f[ks * 8 + ni * 2 + kh] = __uint_as_float(f2tf32(wr[ni * 8]));
            }
        float* wp = g_Wp + ((size_t)(c_wpoff[l] + kt * ntn + nt)) * B_TILE_F + slot * 20;
        *(float4*)(wp)      = *(float4*)(f);
        *(float4*)(wp + 4)  = *(float4*)(f + 4);
        *(float4*)(wp + 8)  = *(float4*)(f + 8);
        *(float4*)(wp + 12) = *(float4*)(f + 12);
    }
}

// ---------------- scan: rowptr + seed fill cursor + reset cnt ----------------
__global__ void scan_kernel() {
    __shared__ int ssum[1024];
    int tid = threadIdx.x;
    int b = tid * 20;
    int vals[20];
    int tot = 0;
    for (int i = 0; i < 20; i++) {
        int idx = b + i;
        vals[i] = (idx < N_NODES) ? g_cnt[idx] : 0;
        tot += vals[i];
    }
    ssum[tid] = tot;
    __syncthreads();
    for (int off = 1; off < 1024; off <<= 1) {
        int t = (tid >= off) ? ssum[tid - off] : 0;
        __syncthreads();
        ssum[tid] += t;
        __syncthreads();
    }
    int run = (tid > 0) ? ssum[tid - 1] : 0;
    for (int i = 0; i < 20; i++) {
        int idx = b + i;
        if (idx < N_NODES) {
            g_rowptr[idx] = run;
            g_fill[idx]   = run;   // fill cursor
            g_cnt[idx]    = 0;     // restore invariant for next replay
            run += vals[i];
        }
    }
    if (tid == 1023) g_rowptr[N_NODES] = run;
}

// ---------------- K3: fill CSR + elr (layer 0 el/er from feat) ----------------
__global__ __launch_bounds__(256) void k3_kernel(
    const int* __restrict__ src, const int* __restrict__ dst,
    const float* __restrict__ feat)
{
    int bid = blockIdx.x;
    if (bid < FILL_B) {
        int e = bid * 256 + threadIdx.x;
        if (e < N_EDGES) {
            int p = atomicAdd(&g_fill[dst[e]], 1);
            g_csrc[p] = src[e];
        }
        return;
    }
    bid -= FILL_B;
    {
        int node = bid * 8 + (threadIdx.x >> 5);
        int lane = threadIdx.x & 31;
        if (node >= N_NODES) return;
        const float4* row = (const float4*)(feat + (size_t)node * 64);
        const float4* wl = (const float4*)g_wal[0];
        const float4* wr = (const float4*)g_war[0];
        float sl = 0.f, sr = 0.f;
        if (lane < 16) {
            float4 v = row[lane];
            float4 a = wl[lane];
            float4 bq = wr[lane];
            sl = v.x * a.x + v.y * a.y + v.z * a.z + v.w * a.w;
            sr = v.x * bq.x + v.y * bq.y + v.z * bq.z + v.w * bq.w;
        }
#pragma unroll
        for (int o = 16; o > 0; o >>= 1) {
            sl += __shfl_down_sync(0xffffffffu, sl, o);
            sr += __shfl_down_sync(0xffffffffu, sr, o);
        }
        if (lane == 0) { g_el[0][node] = sl; g_er[0][node] = sr; }
    }
}

// ---------------- permuted Z offset (fragment-order GEMM A layout) ----------------
__device__ __forceinline__ size_t zp_off(int node, int c, int nkt) {
    int mt = node >> 7, mm = node & 127;
    int wmi = mm >> 6, mr = mm & 63;
    int mi = mr >> 4, rem = mr & 15;
    int g2 = rem & 7, rh = rem >> 3;
    int kt = c >> 4, kk = c & 15;
    int ks = kk >> 3, r = kk & 7;
    int t2 = r & 3, kh = r >> 2;
    return ((size_t)(mt * nkt + kt)) * A_TILE_F
         + (size_t)((wmi * 32 + g2 * 4 + t2) * 36 + ks * 16 + mi * 4 + rh + 2 * kh);
}

// ---------------- fused softmax + weighted gather -> permuted Z ----------------
// reads el/er from elC/erC; zeroes elN/erN for the next layer's epilogue accumulation
__global__ __launch_bounds__(256) void gather_kernel(
    const float* __restrict__ X, float* __restrict__ Zp,
    const float* __restrict__ elC, const float* __restrict__ erC,
    float* __restrict__ elN, float* __restrict__ erN,
    int din, int log2c, int n_nodes)
{
    int wg   = (blockIdx.x * blockDim.x + threadIdx.x) >> 5;
    int lane = threadIdx.x & 31;
    int node  = wg >> log2c;
    int chunk = wg & ((1 << log2c) - 1);
    if (node >= n_nodes) return;
    if (elN && chunk == 0 && lane == 0) { elN[node] = 0.f; erN[node] = 0.f; }
    int c0 = chunk * 64 + lane;
    int beg = g_rowptr[node], end = g_rowptr[node + 1];
    int dg = end - beg;
    int nkt = din >> 4;

    const float* Xc = X + c0;
    float acc0 = 0.f, acc1 = 0.f;

    if (dg > 0) {
        float er_n = erC[node];
        if (dg <= 32) {
            int sreg = 0;
            float e = -INFINITY;
            if (lane < dg) {
                sreg = g_csrc[beg + lane];
                float xx = elC[sreg] + er_n;
                e = xx > 0.f ? xx : 0.2f * xx;
            }
            float m = e;
#pragma unroll
            for (int o = 16; o > 0; o >>= 1)
                m = fmaxf(m, __shfl_xor_sync(0xffffffffu, m, o));
            float w = (lane < dg) ? __expf(e - m) : 0.f;
            float s = w;
#pragma unroll
            for (int o = 16; o > 0; o >>= 1)
                s += __shfl_xor_sync(0xffffffffu, s, o);
            w *= 1.f / s;
#pragma unroll 4
            for (int j = 0; j < dg; j++) {
                int   sj = __shfl_sync(0xffffffffu, sreg, j);
                float wj = __shfl_sync(0xffffffffu, w, j);
                const float* row = Xc + (size_t)sj * din;
                acc0 += wj * row[0];
                acc1 += wj * row[32];
            }
        } else {
            float m = -INFINITY;
            for (int i = beg + lane; i < end; i += 32) {
                float xx = elC[g_csrc[i]] + er_n;
                xx = xx > 0.f ? xx : 0.2f * xx;
                m = fmaxf(m, xx);
            }
#pragma unroll
            for (int o = 16; o > 0; o >>= 1)
                m = fmaxf(m, __shfl_xor_sync(0xffffffffu, m, o));
            float s = 0.f;
            for (int i = beg + lane; i < end; i += 32) {
                float xx = elC[g_csrc[i]] + er_n;
                xx = xx > 0.f ? xx : 0.2f * xx;
                s += __expf(xx - m);
            }
#pragma unroll
            for (int o = 16; o > 0; o >>= 1)
                s += __shfl_xor_sync(0xffffffffu, s, o);
            float inv = 1.f / s;
            for (int base = beg; base < end; base += 32) {
                int n_e = min(32, end - base);
                int sreg = 0; float w = 0.f;
                if (lane < n_e) {
                    sreg = g_csrc[base + lane];
                    float xx = elC[sreg] + er_n;
                    xx = xx > 0.f ? xx : 0.2f * xx;
                    w = __expf(xx - m) * inv;
                }
#pragma unroll 4
                for (int j = 0; j < n_e; j++) {
                    int   sj = __shfl_sync(0xffffffffu, sreg, j);
                    float wj = __shfl_sync(0xffffffffu, w, j);
                    const float* row = Xc + (size_t)sj * din;
                    acc0 += wj * row[0];
                    acc1 += wj * row[32];
                }
            }
        }
    }
    Zp[zp_off(node, c0,      nkt)] = __uint_as_float(f2tf32(acc0));
    Zp[zp_off(node, c0 + 32, nkt)] = __uint_as_float(f2tf32(acc1));
}

// ---------------- tf32 GEMM + fused bias/tanh + next-layer el/er epilogue ----------------
__device__ __forceinline__ void cp_async16(void* smem_dst, const void* gsrc) {
    unsigned s = (unsigned)__cvta_generic_to_shared(smem_dst);
    asm volatile("cp.async.cg.shared.global [%0], [%1], 16;\n" :: "r"(s), "l"(gsrc));
}

__global__ __launch_bounds__(256, 2) void gemm_tf32_kernel(
    const float* __restrict__ Ap, const float* __restrict__ Bp,
    const float* __restrict__ bias, float* __restrict__ C,
    const float* __restrict__ walN, const float* __restrict__ warN,
    float* __restrict__ elN, float* __restrict__ erN,
    int M, int K, int N)
{
    extern __shared__ float smbuf[];
    float* Asm = smbuf;
    float* Bsm = smbuf + 3 * A_TILE_F;

    int tid  = threadIdx.x;
    int lane = tid & 31;
    int warp = tid >> 5;
    int wm = (warp >> 2) * 64;
    int wn = (warp & 3) * 32;
    int g = lane >> 2;
    int t = lane & 3;

    int nkt = K >> 4;
    int ntn = N >> 7;
    int mt = blockIdx.y;
    int nt = blockIdx.x;
    int row0 = mt * GBM;
    int col0 = nt * GBN;

    int aBase = ((warp >> 2) * 32 + lane) * 36;
    int bBase = ((warp & 3) * 32 + lane) * 20;

    float acc[4][4][4];
#pragma unroll
    for (int mi = 0; mi < 4; mi++)
#pragma unroll
        for (int ni = 0; ni < 4; ni++)
#pragma unroll
            for (int r = 0; r < 4; r++) acc[mi][ni][r] = 0.f;

    auto load_stage = [&](int it) {
        int buf = it % 3;
        float* Ab = Asm + buf * A_TILE_F;
        float* Bb = Bsm + buf * B_TILE_F;
        const float* Ag = Ap + ((size_t)(mt * nkt + it)) * A_TILE_F;
        const float* Bg = Bp + ((size_t)(it * ntn + nt)) * B_TILE_F;
#pragma unroll
        for (int i = 0; i < 3; i++) {
            int c = tid + i * 256;
            if (c < A_TILE_F / 4) cp_async16(Ab + c * 4, Ag + c * 4);
        }
#pragma unroll
        for (int i = 0; i < 3; i++) {
            int c = tid + i * 256;
            if (c < B_TILE_F / 4) cp_async16(Bb + c * 4, Bg + c * 4);
        }
        asm volatile("cp.async.commit_group;\n" ::: "memory");
    };

    load_stage(0);
    load_stage(1);

    int nk = nkt;
    for (int it = 0; it < nk; it++) {
        int cur = it % 3;
        if (it + 1 < nk) {
            asm volatile("cp.async.wait_group 1;\n" ::: "memory");
        } else {
            asm volatile("cp.async.wait_group 0;\n" ::: "memory");
        }
        __syncthreads();
        if (it + 2 < nk) load_stage(it + 2);

        const float* Ab = Asm + cur * A_TILE_F;
        const float* Bb = Bsm + cur * B_TILE_F;
#pragma unroll
        for (int ks = 0; ks < 2; ks++) {
            float4 av[4];
#pragma unroll
            for (int mi = 0; mi < 4; mi++)
                av[mi] = *(const float4*)(Ab + aBase + ks * 16 + mi * 4);
            float4 bv0 = *(const float4*)(Bb + bBase + ks * 8);
            float4 bv1 = *(const float4*)(Bb + bBase + ks * 8 + 4);
            unsigned bB[4][2] = {
                {__float_as_uint(bv0.x), __float_as_uint(bv0.y)},
                {__float_as_uint(bv0.z), __float_as_uint(bv0.w)},
                {__float_as_uint(bv1.x), __float_as_uint(bv1.y)},
                {__float_as_uint(bv1.z), __float_as_uint(bv1.w)}};
#pragma unroll
            for (int mi = 0; mi < 4; mi++) {
                unsigned a0 = __float_as_uint(av[mi].x);
                unsigned a1 = __float_as_uint(av[mi].y);
                unsigned a2 = __float_as_uint(av[mi].z);
                unsigned a3 = __float_as_uint(av[mi].w);
#pragma unroll
                for (int ni = 0; ni < 4; ni++) {
                    asm volatile(
                        "mma.sync.aligned.m16n8k8.row.col.f32.tf32.tf32.f32 "
                        "{%0,%1,%2,%3}, {%4,%5,%6,%7}, {%8,%9}, {%0,%1,%2,%3};\n"
                        : "+f"(acc[mi][ni][0]), "+f"(acc[mi][ni][1]),
                          "+f"(acc[mi][ni][2]), "+f"(acc[mi][ni][3])
                        : "r"(a0), "r"(a1), "r"(a2), "r"(a3),
                          "r"(bB[ni][0]), "r"(bB[ni][1]));
                }
            }
        }
    }

    // epilogue: tanh(acc+bias) store + accumulate next-layer el/er partials
#pragma unroll
    for (int mi = 0; mi < 4; mi++) {
        int r0 = row0 + wm + mi * 16 + g;
        int r1 = r0 + 8;
        float sl0 = 0.f, sr0 = 0.f, sl1 = 0.f, sr1 = 0.f;
#pragma unroll
        for (int ni = 0; ni < 4; ni++) {
            int cc = col0 + wn + ni * 8 + 2 * t;
            float b0 = bias[cc], b1 = bias[cc + 1];
            float v0 = tanhf(acc[mi][ni][0] + b0);
            float v1 = tanhf(acc[mi][ni][1] + b1);
            float v2 = tanhf(acc[mi][ni][2] + b0);
            float v3 = tanhf(acc[mi][ni][3] + b1);
            if (r0 < M) {
                C[(size_t)r0 * N + cc]     = v0;
                C[(size_t)r0 * N + cc + 1] = v1;
            }
            if (r1 < M) {
                C[(size_t)r1 * N + cc]     = v2;
                C[(size_t)r1 * N + cc + 1] = v3;
            }
            if (elN) {
                float w0 = walN[cc], w1 = walN[cc + 1];
                float u0 = warN[cc], u1 = warN[cc + 1];
                sl0 += v0 * w0 + v1 * w1;
                sr0 += v0 * u0 + v1 * u1;
                sl1 += v2 * w0 + v3 * w1;
                sr1 += v2 * u0 + v3 * u1;
            }
        }
        if (elN) {
#pragma unroll
            for (int o = 1; o <= 2; o <<= 1) {
                sl0 += __shfl_xor_sync(0xffffffffu, sl0, o);
                sr0 += __shfl_xor_sync(0xffffffffu, sr0, o);
                sl1 += __shfl_xor_sync(0xffffffffu, sl1, o);
                sr1 += __shfl_xor_sync(0xffffffffu, sr1, o);
            }
            if (t == 0) {
                if (r0 < M) { atomicAdd(&elN[r0], sl0); atomicAdd(&erN[r0], sr0); }
                if (r1 < M) { atomicAdd(&elN[r1], sl1); atomicAdd(&erN[r1], sr1); }
            }
        }
    }
}

// ---------------- readout ----------------
// grid (4, 32): per-part partial sums, no atomics, fully overwritten each launch
__global__ void pool_kernel(const float* __restrict__ Y, const int* __restrict__ order) {
    int c = blockIdx.x * blockDim.x + threadIdx.x;
    int part = blockIdx.y;
    int rows = order[0] + 1;
    float s = 0.f;
    for (int r = part; r < rows; r += 32)
        s += Y[(size_t)r * MAXD + c];
    g_poolpart[part * MAXD + c] = s;
}

__global__ __launch_bounds__(1024) void logits_kernel(
    const float* __restrict__ relW, const float* __restrict__ relB,
    const int* __restrict__ rel, const int* __restrict__ order,
    float* __restrict__ out)
{
    __shared__ float sp[MAXD];
    __shared__ float spart[16 * 64];
    __shared__ float lg[64];
    int tid = threadIdx.x;   // 1024
    // sum 32 parts for channel tid
    float s = 0.f;
#pragma unroll
    for (int p = 0; p < 32; p++) s += g_poolpart[p * MAXD + tid];
    sp[tid] = s;
    __syncthreads();
    // 16 subs x 64 outputs
    int sub = tid >> 6, o = tid & 63;
    float a = 0.f;
    int k0 = sub * 64;
    for (int k = k0; k < k0 + 64; k++)
        a += sp[k] * relW[k * 64 + o];
    spart[sub * 64 + o] = a;
    __syncthreads();
    if (tid < 64) {
        float inv = 1.f / (float)(order[0] + 1);
        float v = relB[tid];
        float acc = 0.f;
#pragma unroll
        for (int p = 0; p < 16; p++) acc += spart[p * 64 + tid];
        lg[tid] = v + acc * inv;
    }
    __syncthreads();
    if (tid == 0) {
        int idx[64];
        int cnt = 0;
        for (int i = 0; i < 64; i++)
            if (rel[i] != 0) idx[cnt++] = i;
        for (int k = cnt; k < 64; k++) idx[k] = 0;   // jnp.nonzero pad fill=0
        for (int k = 0; k < 64; k++) out[k] = lg[idx[k]];
    }
}

// ---------------- launch ----------------
extern "C" void kernel_launch(void* const* d_in, const int* in_sizes, int n_in,
                              void* d_out, int out_size)
{
    const float* feat  = (const float*)d_in[0];
    const float* W[4]  = {(const float*)d_in[1], (const float*)d_in[5],
                          (const float*)d_in[9], (const float*)d_in[13]};
    const float* al[4] = {(const float*)d_in[2], (const float*)d_in[6],
                          (const float*)d_in[10], (const float*)d_in[14]};
    const float* ar[4] = {(const float*)d_in[3], (const float*)d_in[7],
                          (const float*)d_in[11], (const float*)d_in[15]};
    const float* bb[4] = {(const float*)d_in[4], (const float*)d_in[8],
                          (const float*)d_in[12], (const float*)d_in[16]};
    const float* relW  = (const float*)d_in[17];
    const float* relB  = (const float*)d_in[18];
    const int*   src   = (const int*)d_in[19];
    const int*   dst   = (const int*)d_in[20];
    const int*   rel   = (const int*)d_in[21];
    const int*   order = (const int*)d_in[22];
    float* out = (float*)d_out;

    float *pA, *pB, *pZ, *pWp, *pWal, *pWar, *pEl, *pEr;
    cudaGetSymbolAddress((void**)&pA,  g_bufA);
    cudaGetSymbolAddress((void**)&pB,  g_bufB);
    cudaGetSymbolAddress((void**)&pZ,  g_Z);
    cudaGetSymbolAddress((void**)&pWp, g_Wp);
    cudaGetSymbolAddress((void**)&pWal, g_wal);
    cudaGetSymbolAddress((void**)&pWar, g_war);
    cudaGetSymbolAddress((void**)&pEl, g_el);
    cudaGetSymbolAddress((void**)&pEr, g_er);

    cudaFuncSetAttribute(gemm_tf32_kernel,
                         cudaFuncAttributeMaxDynamicSharedMemorySize, GEMM_SMEM);

    // K1: count + wv + wperm   (g_cnt==0 invariant holds across replays)
    k1_kernel<<<K1_B, 256>>>(dst,
                             W[0], W[1], W[2], W[3],
                             al[0], al[1], al[2], al[3],
                             ar[0], ar[1], ar[2], ar[3]);
    // scan: rowptr + seed fill cursor + reset cnt
    scan_kernel<<<1, 1024>>>();
    // K3: fill CSR + layer-0 el/er
    k3_kernel<<<K3_B, 256>>>(src, dst, feat);

    const int din_a [4] = {64, 128, 256, 512};
    const int dout_a[4] = {128, 256, 512, 1024};
    const int l2c_a [4] = {0, 1, 2, 3};
    const int wpoff [4] = {0, 4, 20, 84};

    const float* x = feat;
    float* outbufs[4] = {pA, pB, pA, pB};

    for (int l = 0; l < 4; l++) {
        int din = din_a[l], dout = dout_a[l];
        int mrows = (l == 3) ? N_OUT : N_NODES;
        int cur = l & 1, nxt = cur ^ 1;

        float* elN = (l < 3) ? pEl + (size_t)nxt * N_NODES : nullptr;
        float* erN = (l < 3) ? pEr + (size_t)nxt * N_NODES : nullptr;

        int warps = mrows << l2c_a[l];
        gather_kernel<<<(warps * 32 + 255) / 256, 256>>>(
            x, pZ,
            pEl + (size_t)cur * N_NODES, pEr + (size_t)cur * N_NODES,
            elN, erN, din, l2c_a[l], mrows);

        const float* walN = (l < 3) ? pWal + (size_t)(l + 1) * 512 : nullptr;
        const float* warN = (l < 3) ? pWar + (size_t)(l + 1) * 512 : nullptr;

        float* y = outbufs[l];
        dim3 grid(dout / GBN, (mrows + GBM - 1) / GBM);
        gemm_tf32_kernel<<<grid, 256, GEMM_SMEM>>>(
            pZ, pWp + (size_t)wpoff[l] * B_TILE_F, bb[l], y,
            walN, warN, elN, erN, mrows, din, dout);

        x = y;
    }

    dim3 pg(MAXD / 256, 32);
    pool_kernel<<<pg, 256>>>(pB, order);
    logits_kernel<<<1, 1024>>>(relW, relB, rel, order, out);
}

// round 15
// speedup vs baseline: 1.2148x; 1.2148x over previous
#include <cuda_runtime.h>
#include <cuda_bf16.h>
#include <cmath>

#define N_NODES 20000
#define N_EDGES 320000
#define MAXD    1024
#define N_OUT   1024      // layer-4 rows consumed by the readout (order+1)

// GEMM tiling constants
#define GBM 128
#define GBN 128
#define GBK 16
#define A_TILE_F 2304     // 64 lane-slots * 36 floats
#define B_TILE_F 2560     // 128 lane-slots * 20 floats
#define GEMM_SMEM (3 * (A_TILE_F + B_TILE_F) * 4)   // 58368 bytes

// fused prep kernel block ranges
#define FILL_B   1250
#define WV_B     120
#define WPERM_B  2720
#define PREP_B   (FILL_B + WV_B + WPERM_B)

// ---------------- scratch (static __device__, zero-init, no allocs) ----------------
__device__ float g_bufA[(size_t)N_NODES * MAXD];
__device__ float g_bufB[(size_t)N_NODES * MAXD];
__device__ float g_Z  [(size_t)157 * 32 * A_TILE_F];          // permuted GEMM-A
__device__ float g_Wp [(size_t)340 * B_TILE_F];               // permuted GEMM-B, 4 layers
__device__ float g_el[4][N_NODES];   // per-layer el (buf0: elr, buf1-3: gemm epilogue)
__device__ float g_er[4][N_NODES];
__device__ float g_wal[4][512];
__device__ float g_war[4][512];
__device__ int   g_rowptr[N_NODES + 1];
__device__ int   g_cnt[N_NODES];
__device__ int   g_fill[N_NODES];
__device__ int   g_csrc[N_EDGES];
__device__ float g_pool[MAXD];

__device__ __forceinline__ unsigned f2tf32(float f) {
    unsigned u;
    asm("cvt.rna.tf32.f32 %0, %1;" : "=r"(u) : "f"(f));
    return u;
}

__constant__ int c_din[4]  = {64, 128, 256, 512};
__constant__ int c_dout[4] = {128, 256, 512, 1024};
__constant__ int c_wpoff[4] = {0, 4, 20, 84};

// ---------------- CSR zero + el/er buffer zero ----------------
// grid covers 3*N_NODES: i<N_NODES also clears cnt/fill/pool
__global__ void zero_kernel() {
    int i = blockIdx.x * blockDim.x + threadIdx.x;
    if (i < N_NODES) { g_cnt[i] = 0; g_fill[i] = 0; }
    if (i < MAXD) g_pool[i] = 0.f;
    if (i < 3 * N_NODES) {
        (&g_el[1][0])[i] = 0.f;   // zeros g_el[1..3]
        (&g_er[1][0])[i] = 0.f;   // zeros g_er[1..3]
    }
}
__global__ void count_kernel(const int* __restrict__ dst) {
    int e = blockIdx.x * blockDim.x + threadIdx.x;
    if (e < N_EDGES) atomicAdd(&g_cnt[dst[e]], 1);
}
__global__ void scan_kernel() {
    __shared__ int ssum[1024];
    int tid = threadIdx.x;
    int b = tid * 20;
    int tot = 0;
    for (int i = 0; i < 20; i++) {
        int idx = b + i;
        if (idx < N_NODES) {
            g_rowptr[idx] = tot;
            tot += g_cnt[idx];
        }
    }
    ssum[tid] = tot;
    __syncthreads();
    for (int off = 1; off < 1024; off <<= 1) {
        int t = (tid >= off) ? ssum[tid - off] : 0;
        __syncthreads();
        ssum[tid] += t;
        __syncthreads();
    }
    int base = (tid > 0) ? ssum[tid - 1] : 0;
    if (base != 0)
        for (int i = 0; i < 20; i++) {
            int idx = b + i;
            if (idx < N_NODES) g_rowptr[idx] += base;
        }
    if (tid == 1023) g_rowptr[N_NODES] = ssum[1023];
}

// ---------------- fused prep: fill CSR + wv(4 layers) + wperm(4 layers) ----------------
__global__ __launch_bounds__(256) void prep_kernel(
    const int* __restrict__ src, const int* __restrict__ dst,
    const float* __restrict__ W0, const float* __restrict__ W1,
    const float* __restrict__ W2, const float* __restrict__ W3,
    const float* __restrict__ al0, const float* __restrict__ al1,
    const float* __restrict__ al2, const float* __restrict__ al3,
    const float* __restrict__ ar0, const float* __restrict__ ar1,
    const float* __restrict__ ar2, const float* __restrict__ ar3)
{
    const float* Ws[4]  = {W0, W1, W2, W3};
    const float* als[4] = {al0, al1, al2, al3};
    const float* ars[4] = {ar0, ar1, ar2, ar3};
    int bid = blockIdx.x;

    if (bid < FILL_B) {
        int e = bid * 256 + threadIdx.x;
        if (e < N_EDGES) {
            int d = dst[e];
            int p = atomicAdd(&g_fill[d], 1);
            g_csrc[g_rowptr[d] + p] = src[e];
        }
        return;
    }
    bid -= FILL_B;
    if (bid < WV_B) {
        int l, b0;
        if      (bid < 8)  { l = 0; b0 = 0; }
        else if (bid < 24) { l = 1; b0 = 8; }
        else if (bid < 56) { l = 2; b0 = 24; }
        else               { l = 3; b0 = 56; }
        int din = c_din[l], dout = c_dout[l];
        int wid = (bid - b0) * 8 + (threadIdx.x >> 5);
        int lane = threadIdx.x & 31;
        if (wid >= din) return;
        const float* row = Ws[l] + (size_t)wid * dout;
        const float* al = als[l];
        const float* ar = ars[l];
        float sl = 0.f, sr = 0.f;
        for (int j = lane; j < dout; j += 32) {
            float w = row[j];
            sl += w * al[j];
            sr += w * ar[j];
        }
#pragma unroll
        for (int o = 16; o > 0; o >>= 1) {
            sl += __shfl_down_sync(0xffffffffu, sl, o);
            sr += __shfl_down_sync(0xffffffffu, sr, o);
        }
        if (lane == 0) { g_wal[l][wid] = sl; g_war[l][wid] = sr; }
        return;
    }
    bid -= WV_B;
    {
        int l, b0;
        if      (bid < 32)  { l = 0; b0 = 0; }
        else if (bid < 160) { l = 1; b0 = 32; }
        else if (bid < 672) { l = 2; b0 = 160; }
        else                { l = 3; b0 = 672; }
        int din = c_din[l], dout = c_dout[l];
        int i = (bid - b0) * 256 + threadIdx.x;
        if (i >= din * dout) return;
        int k = i / dout, n = i % dout;
        int ntn = dout >> 7;
        int kt = k >> 4, kk = k & 15;
        int ks = kk >> 3, r = kk & 7;
        int t = r & 3, kh = r >> 2;
        int nt = n >> 7, nn = n & 127;
        int wn = nn >> 5, rest = nn & 31;
        int ni = rest >> 3, g = rest & 7;
        size_t off = ((size_t)(c_wpoff[l] + kt * ntn + nt)) * B_TILE_F
                   + (size_t)((wn * 32 + g * 4 + t) * 20 + ks * 8 + ni * 2 + kh);
        g_Wp[off] = __uint_as_float(f2tf32(Ws[l][i]));
    }
}

// ---------------- el / er for layer 0 (from feat) ----------------
__global__ void elr_kernel(const float* __restrict__ X, int din, int l)
{
    int g = blockIdx.x * blockDim.x + threadIdx.x;
    int node = g >> 5, lane = g & 31;
    if (node >= N_NODES) return;
    const float4* row = (const float4*)(X + (size_t)node * din);
    const float4* wl = (const float4*)g_wal[l];
    const float4* wr = (const float4*)g_war[l];
    int nq = din >> 2;
    float sl = 0.f, sr = 0.f;
    for (int c = lane; c < nq; c += 32) {
        float4 v = row[c];
        float4 a = wl[c];
        float4 b = wr[c];
        sl += v.x * a.x + v.y * a.y + v.z * a.z + v.w * a.w;
        sr += v.x * b.x + v.y * b.y + v.z * b.z + v.w * b.w;
    }
#pragma unroll
    for (int o = 16; o > 0; o >>= 1) {
        sl += __shfl_down_sync(0xffffffffu, sl, o);
        sr += __shfl_down_sync(0xffffffffu, sr, o);
    }
    if (lane == 0) { g_el[0][node] = sl; g_er[0][node] = sr; }
}

// ---------------- permuted Z offset (fragment-order GEMM A layout) ----------------
__device__ __forceinline__ size_t zp_off(int node, int c, int nkt) {
    int mt = node >> 7, mm = node & 127;
    int wmi = mm >> 6, mr = mm & 63;
    int mi = mr >> 4, rem = mr & 15;
    int g2 = rem & 7, rh = rem >> 3;
    int kt = c >> 4, kk = c & 15;
    int ks = kk >> 3, r = kk & 7;
    int t2 = r & 3, kh = r >> 2;
    return ((size_t)(mt * nkt + kt)) * A_TILE_F
         + (size_t)((wmi * 32 + g2 * 4 + t2) * 36 + ks * 16 + mi * 4 + rh + 2 * kh);
}

// ---------------- fused softmax + weighted gather -> permuted Z ----------------
__global__ __launch_bounds__(256) void gather_kernel(
    const float* __restrict__ X, float* __restrict__ Zp,
    const float* __restrict__ elC, const float* __restrict__ erC,
    int din, int log2c, int n_nodes)
{
    int wg   = (blockIdx.x * blockDim.x + threadIdx.x) >> 5;
    int lane = threadIdx.x & 31;
    int node  = wg >> log2c;
    int chunk = wg & ((1 << log2c) - 1);
    if (node >= n_nodes) return;
    int c0 = chunk * 64 + lane;
    int beg = g_rowptr[node], end = g_rowptr[node + 1];
    int dg = end - beg;
    int nkt = din >> 4;

    const float* Xc = X + c0;
    float acc0 = 0.f, acc1 = 0.f;

    if (dg > 0) {
        float er_n = erC[node];
        if (dg <= 32) {
            int sreg = 0;
            float e = -INFINITY;
            if (lane < dg) {
                sreg = g_csrc[beg + lane];
                float xx = elC[sreg] + er_n;
                e = xx > 0.f ? xx : 0.2f * xx;
            }
            float m = e;
#pragma unroll
            for (int o = 16; o > 0; o >>= 1)
                m = fmaxf(m, __shfl_xor_sync(0xffffffffu, m, o));
            float w = (lane < dg) ? __expf(e - m) : 0.f;
            float s = w;
#pragma unroll
            for (int o = 16; o > 0; o >>= 1)
                s += __shfl_xor_sync(0xffffffffu, s, o);
            w *= 1.f / s;
#pragma unroll 4
            for (int j = 0; j < dg; j++) {
                int   sj = __shfl_sync(0xffffffffu, sreg, j);
                float wj = __shfl_sync(0xffffffffu, w, j);
                const float* row = Xc + (size_t)sj * din;
                acc0 += wj * row[0];
                acc1 += wj * row[32];
            }
        } else {
            float m = -INFINITY;
            for (int i = beg + lane; i < end; i += 32) {
                float xx = elC[g_csrc[i]] + er_n;
                xx = xx > 0.f ? xx : 0.2f * xx;
                m = fmaxf(m, xx);
            }
#pragma unroll
            for (int o = 16; o > 0; o >>= 1)
                m = fmaxf(m, __shfl_xor_sync(0xffffffffu, m, o));
            float s = 0.f;
            for (int i = beg + lane; i < end; i += 32) {
                float xx = elC[g_csrc[i]] + er_n;
                xx = xx > 0.f ? xx : 0.2f * xx;
                s += __expf(xx - m);
            }
#pragma unroll
            for (int o = 16; o > 0; o >>= 1)
                s += __shfl_xor_sync(0xffffffffu, s, o);
            float inv = 1.f / s;
            for (int base = beg; base < end; base += 32) {
                int n_e = min(32, end - base);
                int sreg = 0; float w = 0.f;
                if (lane < n_e) {
                    sreg = g_csrc[base + lane];
                    float xx = elC[sreg] + er_n;
                    xx = xx > 0.f ? xx : 0.2f * xx;
                    w = __expf(xx - m) * inv;
                }
#pragma unroll 4
                for (int j = 0; j < n_e; j++) {
                    int   sj = __shfl_sync(0xffffffffu, sreg, j);
                    float wj = __shfl_sync(0xffffffffu, w, j);
                    const float* row = Xc + (size_t)sj * din;
                    acc0 += wj * row[0];
                    acc1 += wj * row[32];
                }
            }
        }
    }
    Zp[zp_off(node, c0,      nkt)] = __uint_as_float(f2tf32(acc0));
    Zp[zp_off(node, c0 + 32, nkt)] = __uint_as_float(f2tf32(acc1));
}

// ---------------- tf32 GEMM + fused bias/tanh + next-layer el/er epilogue ----------------
__device__ __forceinline__ void cp_async16(void* smem_dst, const void* gsrc) {
    unsigned s = (unsigned)__cvta_generic_to_shared(smem_dst);
    asm volatile("cp.async.cg.shared.global [%0], [%1], 16;\n" :: "r"(s), "l"(gsrc));
}

__global__ __launch_bounds__(256, 2) void gemm_tf32_kernel(
    const float* __restrict__ Ap, const float* __restrict__ Bp,
    const float* __restrict__ bias, float* __restrict__ C,
    const float* __restrict__ walN, const float* __restrict__ warN,
    float* __restrict__ elN, float* __restrict__ erN,
    int M, int K, int N)
{
    extern __shared__ float smbuf[];
    float* Asm = smbuf;
    float* Bsm = smbuf + 3 * A_TILE_F;

    int tid  = threadIdx.x;
    int lane = tid & 31;
    int warp = tid >> 5;
    int wm = (warp >> 2) * 64;
    int wn = (warp & 3) * 32;
    int g = lane >> 2;
    int t = lane & 3;

    int nkt = K >> 4;
    int ntn = N >> 7;
    int mt = blockIdx.y;
    int nt = blockIdx.x;
    int row0 = mt * GBM;
    int col0 = nt * GBN;

    int aBase = ((warp >> 2) * 32 + lane) * 36;
    int bBase = ((warp & 3) * 32 + lane) * 20;

    float acc[4][4][4];
#pragma unroll
    for (int mi = 0; mi < 4; mi++)
#pragma unroll
        for (int ni = 0; ni < 4; ni++)
#pragma unroll
            for (int r = 0; r < 4; r++) acc[mi][ni][r] = 0.f;

    auto load_stage = [&](int it) {
        int buf = it % 3;
        float* Ab = Asm + buf * A_TILE_F;
        float* Bb = Bsm + buf * B_TILE_F;
        const float* Ag = Ap + ((size_t)(mt * nkt + it)) * A_TILE_F;
        const float* Bg = Bp + ((size_t)(it * ntn + nt)) * B_TILE_F;
#pragma unroll
        for (int i = 0; i < 3; i++) {
            int c = tid + i * 256;
            if (c < A_TILE_F / 4) cp_async16(Ab + c * 4, Ag + c * 4);
        }
#pragma unroll
        for (int i = 0; i < 3; i++) {
            int c = tid + i * 256;
            if (c < B_TILE_F / 4) cp_async16(Bb + c * 4, Bg + c * 4);
        }
        asm volatile("cp.async.commit_group;\n" ::: "memory");
    };

    load_stage(0);
    load_stage(1);

    int nk = nkt;
    for (int it = 0; it < nk; it++) {
        int cur = it % 3;
        if (it + 1 < nk) {
            asm volatile("cp.async.wait_group 1;\n" ::: "memory");
        } else {
            asm volatile("cp.async.wait_group 0;\n" ::: "memory");
        }
        __syncthreads();
        if (it + 2 < nk) load_stage(it + 2);

        const float* Ab = Asm + cur * A_TILE_F;
        const float* Bb = Bsm + cur * B_TILE_F;
#pragma unroll
        for (int ks = 0; ks < 2; ks++) {
            float4 av[4];
#pragma unroll
            for (int mi = 0; mi < 4; mi++)
                av[mi] = *(const float4*)(Ab + aBase + ks * 16 + mi * 4);
            float4 bv0 = *(const float4*)(Bb + bBase + ks * 8);
            float4 bv1 = *(const float4*)(Bb + bBase + ks * 8 + 4);
            unsigned bB[4][2] = {
                {__float_as_uint(bv0.x), __float_as_uint(bv0.y)},
                {__float_as_uint(bv0.z), __float_as_uint(bv0.w)},
                {__float_as_uint(bv1.x), __float_as_uint(bv1.y)},
                {__float_as_uint(bv1.z), __float_as_uint(bv1.w)}};
#pragma unroll
            for (int mi = 0; mi < 4; mi++) {
                unsigned a0 = __float_as_uint(av[mi].x);
                unsigned a1 = __float_as_uint(av[mi].y);
                unsigned a2 = __float_as_uint(av[mi].z);
                unsigned a3 = __float_as_uint(av[mi].w);
#pragma unroll
                for (int ni = 0; ni < 4; ni++) {
                    asm volatile(
                        "mma.sync.aligned.m16n8k8.row.col.f32.tf32.tf32.f32 "
                        "{%0,%1,%2,%3}, {%4,%5,%6,%7}, {%8,%9}, {%0,%1,%2,%3};\n"
                        : "+f"(acc[mi][ni][0]), "+f"(acc[mi][ni][1]),
                          "+f"(acc[mi][ni][2]), "+f"(acc[mi][ni][3])
                        : "r"(a0), "r"(a1), "r"(a2), "r"(a3),
                          "r"(bB[ni][0]), "r"(bB[ni][1]));
                }
            }
        }
    }

    // epilogue: tanh(acc+bias) store + accumulate next-layer el/er partials
#pragma unroll
    for (int mi = 0; mi < 4; mi++) {
        int r0 = row0 + wm + mi * 16 + g;
        int r1 = r0 + 8;
        float sl0 = 0.f, sr0 = 0.f, sl1 = 0.f, sr1 = 0.f;
#pragma unroll
        for (int ni = 0; ni < 4; ni++) {
            int cc = col0 + wn + ni * 8 + 2 * t;
            float b0 = bias[cc], b1 = bias[cc + 1];
            float v0 = tanhf(acc[mi][ni][0] + b0);
            float v1 = tanhf(acc[mi][ni][1] + b1);
            float v2 = tanhf(acc[mi][ni][2] + b0);
            float v3 = tanhf(acc[mi][ni][3] + b1);
            if (r0 < M) {
                C[(size_t)r0 * N + cc]     = v0;
                C[(size_t)r0 * N + cc + 1] = v1;
            }
            if (r1 < M) {
                C[(size_t)r1 * N + cc]     = v2;
                C[(size_t)r1 * N + cc + 1] = v3;
            }
            if (elN) {
                float w0 = walN[cc], w1 = walN[cc + 1];
                float u0 = warN[cc], u1 = warN[cc + 1];
                sl0 += v0 * w0 + v1 * w1;
                sr0 += v0 * u0 + v1 * u1;
                sl1 += v2 * w0 + v3 * w1;
                sr1 += v2 * u0 + v3 * u1;
            }
        }
        if (elN) {
#pragma unroll
            for (int o = 1; o <= 2; o <<= 1) {
                sl0 += __shfl_xor_sync(0xffffffffu, sl0, o);
                sr0 += __shfl_xor_sync(0xffffffffu, sr0, o);
                sl1 += __shfl_xor_sync(0xffffffffu, sl1, o);
                sr1 += __shfl_xor_sync(0xffffffffu, sr1, o);
            }
            if (t == 0) {
                if (r0 < M) { atomicAdd(&elN[r0], sl0); atomicAdd(&erN[r0], sr0); }
                if (r1 < M) { atomicAdd(&elN[r1], sl1); atomicAdd(&erN[r1], sr1); }
            }
        }
    }
}

// ---------------- readout ----------------
__global__ void pool_kernel(const float* __restrict__ Y, const int* __restrict__ order) {
    int c = blockIdx.x * blockDim.x + threadIdx.x;
    int rows = order[0] + 1;
    float s = 0.f;
    for (int r = blockIdx.y; r < rows; r += 32)
        s += Y[(size_t)r * MAXD + c];
    atomicAdd(&g_pool[c], s);
}

__global__ void logits_kernel(const float* __restrict__ relW,
                              const float* __restrict__ relB,
                              const int* __restrict__ rel,
                              const int* __restrict__ order,
                              float* __restrict__ out)
{
    int t = threadIdx.x;   // 64 threads
    float inv = 1.f / (float)(order[0] + 1);
    float s = relB[t];
    for (int k = 0; k < MAXD; k++) s += (g_pool[k] * inv) * relW[k * 64 + t];
    __shared__ float lg[64];
    lg[t] = s;
    __syncthreads();
    if (t == 0) {
        int idx[64];
        int cnt = 0;
        for (int i = 0; i < 64; i++)
            if (rel[i] != 0) idx[cnt++] = i;
        for (int k = cnt; k < 64; k++) idx[k] = 0;   // jnp.nonzero pad fill=0
        for (int k = 0; k < 64; k++) out[k] = lg[idx[k]];
    }
}

// ---------------- launch ----------------
extern "C" void kernel_launch(void* const* d_in, const int* in_sizes, int n_in,
                              void* d_out, int out_size)
{
    const float* feat  = (const float*)d_in[0];
    const float* W[4]  = {(const float*)d_in[1], (const float*)d_in[5],
                          (const float*)d_in[9], (const float*)d_in[13]};
    const float* al[4] = {(const float*)d_in[2], (const float*)d_in[6],
                          (const float*)d_in[10], (const float*)d_in[14]};
    const float* ar[4] = {(const float*)d_in[3], (const float*)d_in[7],
                          (const float*)d_in[11], (const float*)d_in[15]};
    const float* bb[4] = {(const float*)d_in[4], (const float*)d_in[8],
                          (const float*)d_in[12], (const float*)d_in[16]};
    const float* relW  = (const float*)d_in[17];
    const float* relB  = (const float*)d_in[18];
    const int*   src   = (const int*)d_in[19];
    const int*   dst   = (const int*)d_in[20];
    const int*   rel   = (const int*)d_in[21];
    const int*   order = (const int*)d_in[22];
    float* out = (float*)d_out;

    float *pA, *pB, *pZ, *pWp, *pWal, *pWar, *pEl, *pEr;
    cudaGetSymbolAddress((void**)&pA,  g_bufA);
    cudaGetSymbolAddress((void**)&pB,  g_bufB);
    cudaGetSymbolAddress((void**)&pZ,  g_Z);
    cudaGetSymbolAddress((void**)&pWp, g_Wp);
    cudaGetSymbolAddress((void**)&pWal, g_wal);
    cudaGetSymbolAddress((void**)&pWar, g_war);
    cudaGetSymbolAddress((void**)&pEl, g_el);
    cudaGetSymbolAddress((void**)&pEr, g_er);

    cudaFuncSetAttribute(gemm_tf32_kernel,
                         cudaFuncAttributeMaxDynamicSharedMemorySize, GEMM_SMEM);

    // CSR + el/er buffer zero + W-prep
    zero_kernel <<<(3 * N_NODES + 255) / 256, 256>>>();
    count_kernel<<<(N_EDGES + 255) / 256, 256>>>(dst);
    scan_kernel <<<1, 1024>>>();
    prep_kernel <<<PREP_B, 256>>>(src, dst,
                                  W[0], W[1], W[2], W[3],
                                  al[0], al[1], al[2], al[3],
                                  ar[0], ar[1], ar[2], ar[3]);

    const int din_a [4] = {64, 128, 256, 512};
    const int dout_a[4] = {128, 256, 512, 1024};
    const int l2c_a [4] = {0, 1, 2, 3};
    const int wpoff [4] = {0, 4, 20, 84};

    // el/er for layer 0 from feat
    elr_kernel<<<(N_NODES * 32 + 255) / 256, 256>>>(feat, 64, 0);

    const float* x = feat;
    float* outbufs[4] = {pA, pB, pA, pB};

    for (int l = 0; l < 4; l++) {
        int din = din_a[l], dout = dout_a[l];
        int mrows = (l == 3) ? N_OUT : N_NODES;

        // fused softmax + gather reads this layer's el/er buffer
        int warps = mrows << l2c_a[l];
        gather_kernel<<<(warps * 32 + 255) / 256, 256>>>(
            x, pZ, pEl + (size_t)l * N_NODES, pEr + (size_t)l * N_NODES,
            din, l2c_a[l], mrows);

        // epilogue accumulates next layer's el/er into its own pre-zeroed buffer
        const float* walN = nullptr;
        const float* warN = nullptr;
        float* elN = nullptr;
        float* erN = nullptr;
        if (l < 3) {
            walN = pWal + (size_t)(l + 1) * 512;
            warN = pWar + (size_t)(l + 1) * 512;
            elN  = pEl + (size_t)(l + 1) * N_NODES;
            erN  = pEr + (size_t)(l + 1) * N_NODES;
        }

        float* y = outbufs[l];
        dim3 grid(dout / GBN, (mrows + GBM - 1) / GBM);
        gemm_tf32_kernel<<<grid, 256, GEMM_SMEM>>>(
            pZ, pWp + (size_t)wpoff[l] * B_TILE_F, bb[l], y,
            walN, warN, elN, erN, mrows, din, dout);

        x = y;
    }

    dim3 pg(MAXD / 256, 32);
    pool_kernel<<<pg, 256>>>(pB, order);
    logits_kernel<<<1, 64>>>(relW, relB, rel, order, out);
}

// round 17
// speedup vs baseline: 1.2648x; 1.0412x over previous
#include <cuda_runtime.h>
#include <cuda_bf16.h>
#include <cmath>

#define N_NODES 20000
#define N_EDGES 320000
#define MAXD    1024
#define N_OUT   1024      // layer-4 rows consumed by the readout (order+1)

// GEMM tiling constants
#define GBM 128
#define GBN 128
#define GBK 16
#define A_TILE_F 2304     // 64 lane-slots * 36 floats
#define B_TILE_F 2560     // 128 lane-slots * 20 floats
#define GEMM_SMEM (3 * (A_TILE_F + B_TILE_F) * 4)   // 58368 bytes

// fused prep kernel block ranges
#define FILL_B   1250
#define WV_B     120
#define WPERM_B  2720
#define PREP_B   (FILL_B + WV_B + WPERM_B)

// ---------------- scratch (static __device__, zero-init, no allocs) ----------------
__device__ float g_bufA[(size_t)N_NODES * MAXD];
__device__ float g_bufB[(size_t)N_NODES * MAXD];
__device__ float g_Z  [(size_t)157 * 32 * A_TILE_F];          // permuted GEMM-A
__device__ float g_Wp [(size_t)340 * B_TILE_F];               // permuted GEMM-B, 4 layers
__device__ float g_el[4][N_NODES];   // per-layer el (buf0: elr, buf1-3: gemm epilogue)
__device__ float g_er[4][N_NODES];
__device__ float g_wal[4][512];
__device__ float g_war[4][512];
__device__ int   g_rowptr[N_NODES + 1];
__device__ int   g_cnt[N_NODES];
__device__ int   g_fill[N_NODES];
__device__ int   g_csrc[N_EDGES];
__device__ float g_pool[MAXD];

__device__ __forceinline__ unsigned f2tf32(float f) {
    unsigned u;
    asm("cvt.rna.tf32.f32 %0, %1;" : "=r"(u) : "f"(f));
    return u;
}

__constant__ int c_din[4]  = {64, 128, 256, 512};
__constant__ int c_dout[4] = {128, 256, 512, 1024};
__constant__ int c_wpoff[4] = {0, 4, 20, 84};

// ---------------- CSR zero + el/er buffer zero ----------------
__global__ void zero_kernel() {
    int i = blockIdx.x * blockDim.x + threadIdx.x;
    if (i < N_NODES) { g_cnt[i] = 0; g_fill[i] = 0; }
    if (i < MAXD) g_pool[i] = 0.f;
    if (i < 3 * N_NODES) {
        (&g_el[1][0])[i] = 0.f;
        (&g_er[1][0])[i] = 0.f;
    }
}
__global__ void count_kernel(const int* __restrict__ dst) {
    int e = blockIdx.x * blockDim.x + threadIdx.x;
    if (e < N_EDGES) atomicAdd(&g_cnt[dst[e]], 1);
}
__global__ void scan_kernel() {
    __shared__ int ssum[1024];
    int tid = threadIdx.x;
    int b = tid * 20;
    int tot = 0;
    for (int i = 0; i < 20; i++) {
        int idx = b + i;
        if (idx < N_NODES) {
            g_rowptr[idx] = tot;
            tot += g_cnt[idx];
        }
    }
    ssum[tid] = tot;
    __syncthreads();
    for (int off = 1; off < 1024; off <<= 1) {
        int t = (tid >= off) ? ssum[tid - off] : 0;
        __syncthreads();
        ssum[tid] += t;
        __syncthreads();
    }
    int base = (tid > 0) ? ssum[tid - 1] : 0;
    if (base != 0)
        for (int i = 0; i < 20; i++) {
            int idx = b + i;
            if (idx < N_NODES) g_rowptr[idx] += base;
        }
    if (tid == 1023) g_rowptr[N_NODES] = ssum[1023];
}

// ---------------- fused prep: fill CSR + wv(4 layers) + wperm(4 layers) ----------------
__global__ __launch_bounds__(256) void prep_kernel(
    const int* __restrict__ src, const int* __restrict__ dst,
    const float* __restrict__ W0, const float* __restrict__ W1,
    const float* __restrict__ W2, const float* __restrict__ W3,
    const float* __restrict__ al0, const float* __restrict__ al1,
    const float* __restrict__ al2, const float* __restrict__ al3,
    const float* __restrict__ ar0, const float* __restrict__ ar1,
    const float* __restrict__ ar2, const float* __restrict__ ar3)
{
    const float* Ws[4]  = {W0, W1, W2, W3};
    const float* als[4] = {al0, al1, al2, al3};
    const float* ars[4] = {ar0, ar1, ar2, ar3};
    int bid = blockIdx.x;

    if (bid < FILL_B) {
        int e = bid * 256 + threadIdx.x;
        if (e < N_EDGES) {
            int d = dst[e];
            int p = atomicAdd(&g_fill[d], 1);
            g_csrc[g_rowptr[d] + p] = src[e];
        }
        return;
    }
    bid -= FILL_B;
    if (bid < WV_B) {
        int l, b0;
        if      (bid < 8)  { l = 0; b0 = 0; }
        else if (bid < 24) { l = 1; b0 = 8; }
        else if (bid < 56) { l = 2; b0 = 24; }
        else               { l = 3; b0 = 56; }
        int din = c_din[l], dout = c_dout[l];
        int wid = (bid - b0) * 8 + (threadIdx.x >> 5);
        int lane = threadIdx.x & 31;
        if (wid >= din) return;
        const float* row = Ws[l] + (size_t)wid * dout;
        const float* al = als[l];
        const float* ar = ars[l];
        float sl = 0.f, sr = 0.f;
        for (int j = lane; j < dout; j += 32) {
            float w = row[j];
            sl += w * al[j];
            sr += w * ar[j];
        }
#pragma unroll
        for (int o = 16; o > 0; o >>= 1) {
            sl += __shfl_down_sync(0xffffffffu, sl, o);
            sr += __shfl_down_sync(0xffffffffu, sr, o);
        }
        if (lane == 0) { g_wal[l][wid] = sl; g_war[l][wid] = sr; }
        return;
    }
    bid -= WV_B;
    {
        int l, b0;
        if      (bid < 32)  { l = 0; b0 = 0; }
        else if (bid < 160) { l = 1; b0 = 32; }
        else if (bid < 672) { l = 2; b0 = 160; }
        else                { l = 3; b0 = 672; }
        int din = c_din[l], dout = c_dout[l];
        int i = (bid - b0) * 256 + threadIdx.x;
        if (i >= din * dout) return;
        int k = i / dout, n = i % dout;
        int ntn = dout >> 7;
        int kt = k >> 4, kk = k & 15;
        int ks = kk >> 3, r = kk & 7;
        int t = r & 3, kh = r >> 2;
        int nt = n >> 7, nn = n & 127;
        int wn = nn >> 5, rest = nn & 31;
        int ni = rest >> 3, g = rest & 7;
        size_t off = ((size_t)(c_wpoff[l] + kt * ntn + nt)) * B_TILE_F
                   + (size_t)((wn * 32 + g * 4 + t) * 20 + ks * 8 + ni * 2 + kh);
        g_Wp[off] = __uint_as_float(f2tf32(Ws[l][i]));
    }
}

// ---------------- el / er for layer 0 (from feat) ----------------
__global__ void elr_kernel(const float* __restrict__ X, int din, int l)
{
    int g = blockIdx.x * blockDim.x + threadIdx.x;
    int node = g >> 5, lane = g & 31;
    if (node >= N_NODES) return;
    const float4* row = (const float4*)(X + (size_t)node * din);
    const float4* wl = (const float4*)g_wal[l];
    const float4* wr = (const float4*)g_war[l];
    int nq = din >> 2;
    float sl = 0.f, sr = 0.f;
    for (int c = lane; c < nq; c += 32) {
        float4 v = row[c];
        float4 a = wl[c];
        float4 b = wr[c];
        sl += v.x * a.x + v.y * a.y + v.z * a.z + v.w * a.w;
        sr += v.x * b.x + v.y * b.y + v.z * b.z + v.w * b.w;
    }
#pragma unroll
    for (int o = 16; o > 0; o >>= 1) {
        sl += __shfl_down_sync(0xffffffffu, sl, o);
        sr += __shfl_down_sync(0xffffffffu, sr, o);
    }
    if (lane == 0) { g_el[0][node] = sl; g_er[0][node] = sr; }
}

// ---------------- permuted Z offset (fragment-order GEMM A layout) ----------------
__device__ __forceinline__ size_t zp_off(int node, int c, int nkt) {
    int mt = node >> 7, mm = node & 127;
    int wmi = mm >> 6, mr = mm & 63;
    int mi = mr >> 4, rem = mr & 15;
    int g2 = rem & 7, rh = rem >> 3;
    int kt = c >> 4, kk = c & 15;
    int ks = kk >> 3, r = kk & 7;
    int t2 = r & 3, kh = r >> 2;
    return ((size_t)(mt * nkt + kt)) * A_TILE_F
         + (size_t)((wmi * 32 + g2 * 4 + t2) * 36 + ks * 16 + mi * 4 + rh + 2 * kh);
}

// ---------------- fused softmax + weighted gather -> permuted Z ----------------
// VEC channels per lane (VEC=2: 64ch/warp for din=64; VEC=4: 128ch/warp for din>=128)
template <int VEC>
__global__ __launch_bounds__(256) void gather_kernel(
    const float* __restrict__ X, float* __restrict__ Zp,
    const float* __restrict__ elC, const float* __restrict__ erC,
    int din, int log2c, int n_nodes)
{
    int wg   = (blockIdx.x * blockDim.x + threadIdx.x) >> 5;
    int lane = threadIdx.x & 31;
    int node  = wg >> log2c;
    int chunk = wg & ((1 << log2c) - 1);
    if (node >= n_nodes) return;
    int c0 = chunk * (32 * VEC) + lane * VEC;
    int beg = g_rowptr[node], end = g_rowptr[node + 1];
    int dg = end - beg;
    int nkt = din >> 4;

    const float* Xc = X + c0;
    float acc[VEC];
#pragma unroll
    for (int v = 0; v < VEC; v++) acc[v] = 0.f;

    if (dg > 0) {
        float er_n = erC[node];
        if (dg <= 32) {
            int sreg = 0;
            float e = -INFINITY;
            if (lane < dg) {
                sreg = g_csrc[beg + lane];
                float xx = elC[sreg] + er_n;
                e = xx > 0.f ? xx : 0.2f * xx;
            }
            float m = e;
#pragma unroll
            for (int o = 16; o > 0; o >>= 1)
                m = fmaxf(m, __shfl_xor_sync(0xffffffffu, m, o));
            float w = (lane < dg) ? __expf(e - m) : 0.f;
            float s = w;
#pragma unroll
            for (int o = 16; o > 0; o >>= 1)
                s += __shfl_xor_sync(0xffffffffu, s, o);
            w *= 1.f / s;
#pragma unroll 4
            for (int j = 0; j < dg; j++) {
                int   sj = __shfl_sync(0xffffffffu, sreg, j);
                float wj = __shfl_sync(0xffffffffu, w, j);
                const float* row = Xc + (size_t)sj * din;
                if (VEC == 4) {
                    float4 v = *(const float4*)row;
                    acc[0] += wj * v.x; acc[1] += wj * v.y;
                    acc[2] += wj * v.z; acc[3] += wj * v.w;
                } else {
                    float2 v = *(const float2*)row;
                    acc[0] += wj * v.x; acc[1] += wj * v.y;
                }
            }
        } else {
            float m = -INFINITY;
            for (int i = beg + lane; i < end; i += 32) {
                float xx = elC[g_csrc[i]] + er_n;
                xx = xx > 0.f ? xx : 0.2f * xx;
                m = fmaxf(m, xx);
            }
#pragma unroll
            for (int o = 16; o > 0; o >>= 1)
                m = fmaxf(m, __shfl_xor_sync(0xffffffffu, m, o));
            float s = 0.f;
            for (int i = beg + lane; i < end; i += 32) {
                float xx = elC[g_csrc[i]] + er_n;
                xx = xx > 0.f ? xx : 0.2f * xx;
                s += __expf(xx - m);
            }
#pragma unroll
            for (int o = 16; o > 0; o >>= 1)
                s += __shfl_xor_sync(0xffffffffu, s, o);
            float inv = 1.f / s;
            for (int base = beg; base < end; base += 32) {
                int n_e = min(32, end - base);
                int sreg = 0; float w = 0.f;
                if (lane < n_e) {
                    sreg = g_csrc[base + lane];
                    float xx = elC[sreg] + er_n;
                    xx = xx > 0.f ? xx : 0.2f * xx;
                    w = __expf(xx - m) * inv;
                }
#pragma unroll 4
                for (int j = 0; j < n_e; j++) {
                    int   sj = __shfl_sync(0xffffffffu, sreg, j);
                    float wj = __shfl_sync(0xffffffffu, w, j);
                    const float* row = Xc + (size_t)sj * din;
                    if (VEC == 4) {
                        float4 v = *(const float4*)row;
                        acc[0] += wj * v.x; acc[1] += wj * v.y;
                        acc[2] += wj * v.z; acc[3] += wj * v.w;
                    } else {
                        float2 v = *(const float2*)row;
                        acc[0] += wj * v.x; acc[1] += wj * v.y;
                    }
                }
            }
        }
    }
#pragma unroll
    for (int v = 0; v < VEC; v++)
        Zp[zp_off(node, c0 + v, nkt)] = __uint_as_float(f2tf32(acc[v]));
}

// ---------------- tf32 GEMM + fused bias/tanh + next-layer el/er epilogue ----------------
__device__ __forceinline__ void cp_async16(void* smem_dst, const void* gsrc) {
    unsigned s = (unsigned)__cvta_generic_to_shared(smem_dst);
    asm volatile("cp.async.cg.shared.global [%0], [%1], 16;\n" :: "r"(s), "l"(gsrc));
}

__global__ __launch_bounds__(256, 2) void gemm_tf32_kernel(
    const float* __restrict__ Ap, const float* __restrict__ Bp,
    const float* __restrict__ bias, float* __restrict__ C,
    const float* __restrict__ walN, const float* __restrict__ warN,
    float* __restrict__ elN, float* __restrict__ erN,
    int M, int K, int N)
{
    extern __shared__ float smbuf[];
    float* Asm = smbuf;
    float* Bsm = smbuf + 3 * A_TILE_F;

    int tid  = threadIdx.x;
    int lane = tid & 31;
    int warp = tid >> 5;
    int wm = (warp >> 2) * 64;
    int wn = (warp & 3) * 32;
    int g = lane >> 2;
    int t = lane & 3;

    int nkt = K >> 4;
    int ntn = N >> 7;
    int mt = blockIdx.y;
    int nt = blockIdx.x;
    int row0 = mt * GBM;
    int col0 = nt * GBN;

    int aBase = ((warp >> 2) * 32 + lane) * 36;
    int bBase = ((warp & 3) * 32 + lane) * 20;

    float acc[4][4][4];
#pragma unroll
    for (int mi = 0; mi < 4; mi++)
#pragma unroll
        for (int ni = 0; ni < 4; ni++)
#pragma unroll
            for (int r = 0; r < 4; r++) acc[mi][ni][r] = 0.f;

    auto load_stage = [&](int it) {
        int buf = it % 3;
        float* Ab = Asm + buf * A_TILE_F;
        float* Bb = Bsm + buf * B_TILE_F;
        const float* Ag = Ap + ((size_t)(mt * nkt + it)) * A_TILE_F;
        const float* Bg = Bp + ((size_t)(it * ntn + nt)) * B_TILE_F;
#pragma unroll
        for (int i = 0; i < 3; i++) {
            int c = tid + i * 256;
            if (c < A_TILE_F / 4) cp_async16(Ab + c * 4, Ag + c * 4);
        }
#pragma unroll
        for (int i = 0; i < 3; i++) {
            int c = tid + i * 256;
            if (c < B_TILE_F / 4) cp_async16(Bb + c * 4, Bg + c * 4);
        }
        asm volatile("cp.async.commit_group;\n" ::: "memory");
    };

    load_stage(0);
    load_stage(1);

    int nk = nkt;
    for (int it = 0; it < nk; it++) {
        int cur = it % 3;
        if (it + 1 < nk) {
            asm volatile("cp.async.wait_group 1;\n" ::: "memory");
        } else {
            asm volatile("cp.async.wait_group 0;\n" ::: "memory");
        }
        __syncthreads();
        if (it + 2 < nk) load_stage(it + 2);

        const float* Ab = Asm + cur * A_TILE_F;
        const float* Bb = Bsm + cur * B_TILE_F;
#pragma unroll
        for (int ks = 0; ks < 2; ks++) {
            float4 av[4];
#pragma unroll
            for (int mi = 0; mi < 4; mi++)
                av[mi] = *(const float4*)(Ab + aBase + ks * 16 + mi * 4);
            float4 bv0 = *(const float4*)(Bb + bBase + ks * 8);
            float4 bv1 = *(const float4*)(Bb + bBase + ks * 8 + 4);
            unsigned bB[4][2] = {
                {__float_as_uint(bv0.x), __float_as_uint(bv0.y)},
                {__float_as_uint(bv0.z), __float_as_uint(bv0.w)},
                {__float_as_uint(bv1.x), __float_as_uint(bv1.y)},
                {__float_as_uint(bv1.z), __float_as_uint(bv1.w)}};
#pragma unroll
            for (int mi = 0; mi < 4; mi++) {
                unsigned a0 = __float_as_uint(av[mi].x);
                unsigned a1 = __float_as_uint(av[mi].y);
                unsigned a2 = __float_as_uint(av[mi].z);
                unsigned a3 = __float_as_uint(av[mi].w);
#pragma unroll
                for (int ni = 0; ni < 4; ni++) {
                    asm volatile(
                        "mma.sync.aligned.m16n8k8.row.col.f32.tf32.tf32.f32 "
                        "{%0,%1,%2,%3}, {%4,%5,%6,%7}, {%8,%9}, {%0,%1,%2,%3};\n"
                        : "+f"(acc[mi][ni][0]), "+f"(acc[mi][ni][1]),
                          "+f"(acc[mi][ni][2]), "+f"(acc[mi][ni][3])
                        : "r"(a0), "r"(a1), "r"(a2), "r"(a3),
                          "r"(bB[ni][0]), "r"(bB[ni][1]));
                }
            }
        }
    }

    // epilogue: tanh(acc+bias) store + accumulate next-layer el/er partials
#pragma unroll
    for (int mi = 0; mi < 4; mi++) {
        int r0 = row0 + wm + mi * 16 + g;
        int r1 = r0 + 8;
        float sl0 = 0.f, sr0 = 0.f, sl1 = 0.f, sr1 = 0.f;
#pragma unroll
        for (int ni = 0; ni < 4; ni++) {
            int cc = col0 + wn + ni * 8 + 2 * t;
            float b0 = bias[cc], b1 = bias[cc + 1];
            float v0 = tanhf(acc[mi][ni][0] + b0);
            float v1 = tanhf(acc[mi][ni][1] + b1);
            float v2 = tanhf(acc[mi][ni][2] + b0);
            float v3 = tanhf(acc[mi][ni][3] + b1);
            if (r0 < M) {
                C[(size_t)r0 * N + cc]     = v0;
                C[(size_t)r0 * N + cc + 1] = v1;
            }
            if (r1 < M) {
                C[(size_t)r1 * N + cc]     = v2;
                C[(size_t)r1 * N + cc + 1] = v3;
            }
            if (elN) {
                float w0 = walN[cc], w1 = walN[cc + 1];
                float u0 = warN[cc], u1 = warN[cc + 1];
                sl0 += v0 * w0 + v1 * w1;
                sr0 += v0 * u0 + v1 * u1;
                sl1 += v2 * w0 + v3 * w1;
                sr1 += v2 * u0 + v3 * u1;
            }
        }
        if (elN) {
#pragma unroll
            for (int o = 1; o <= 2; o <<= 1) {
                sl0 += __shfl_xor_sync(0xffffffffu, sl0, o);
                sr0 += __shfl_xor_sync(0xffffffffu, sr0, o);
                sl1 += __shfl_xor_sync(0xffffffffu, sl1, o);
                sr1 += __shfl_xor_sync(0xffffffffu, sr1, o);
            }
            if (t == 0) {
                if (r0 < M) { atomicAdd(&elN[r0], sl0); atomicAdd(&erN[r0], sr0); }
                if (r1 < M) { atomicAdd(&elN[r1], sl1); atomicAdd(&erN[r1], sr1); }
            }
        }
    }
}

// ---------------- readout ----------------
__global__ void pool_kernel(const float* __restrict__ Y, const int* __restrict__ order) {
    int c = blockIdx.x * blockDim.x + threadIdx.x;
    int rows = order[0] + 1;
    float s = 0.f;
    for (int r = blockIdx.y; r < rows; r += 32)
        s += Y[(size_t)r * MAXD + c];
    atomicAdd(&g_pool[c], s);
}

__global__ void logits_kernel(const float* __restrict__ relW,
                              const float* __restrict__ relB,
                              const int* __restrict__ rel,
                              const int* __restrict__ order,
                              float* __restrict__ out)
{
    int t = threadIdx.x;   // 64 threads
    float inv = 1.f / (float)(order[0] + 1);
    float s = relB[t];
    for (int k = 0; k < MAXD; k++) s += (g_pool[k] * inv) * relW[k * 64 + t];
    __shared__ float lg[64];
    lg[t] = s;
    __syncthreads();
    if (t == 0) {
        int idx[64];
        int cnt = 0;
        for (int i = 0; i < 64; i++)
            if (rel[i] != 0) idx[cnt++] = i;
        for (int k = cnt; k < 64; k++) idx[k] = 0;   // jnp.nonzero pad fill=0
        for (int k = 0; k < 64; k++) out[k] = lg[idx[k]];
    }
}

// ---------------- launch ----------------
extern "C" void kernel_launch(void* const* d_in, const int* in_sizes, int n_in,
                              void* d_out, int out_size)
{
    const float* feat  = (const float*)d_in[0];
    const float* W[4]  = {(const float*)d_in[1], (const float*)d_in[5],
                          (const float*)d_in[9], (const float*)d_in[13]};
    const float* al[4] = {(const float*)d_in[2], (const float*)d_in[6],
                          (const float*)d_in[10], (const float*)d_in[14]};
    const float* ar[4] = {(const float*)d_in[3], (const float*)d_in[7],
                          (const float*)d_in[11], (const float*)d_in[15]};
    const float* bb[4] = {(const float*)d_in[4], (const float*)d_in[8],
                          (const float*)d_in[12], (const float*)d_in[16]};
    const float* relW  = (const float*)d_in[17];
    const float* relB  = (const float*)d_in[18];
    const int*   src   = (const int*)d_in[19];
    const int*   dst   = (const int*)d_in[20];
    const int*   rel   = (const int*)d_in[21];
    const int*   order = (const int*)d_in[22];
    float* out = (float*)d_out;

    float *pA, *pB, *pZ, *pWp, *pWal, *pWar, *pEl, *pEr;
    cudaGetSymbolAddress((void**)&pA,  g_bufA);
    cudaGetSymbolAddress((void**)&pB,  g_bufB);
    cudaGetSymbolAddress((void**)&pZ,  g_Z);
    cudaGetSymbolAddress((void**)&pWp, g_Wp);
    cudaGetSymbolAddress((void**)&pWal, g_wal);
    cudaGetSymbolAddress((void**)&pWar, g_war);
    cudaGetSymbolAddress((void**)&pEl, g_el);
    cudaGetSymbolAddress((void**)&pEr, g_er);

    cudaFuncSetAttribute(gemm_tf32_kernel,
                         cudaFuncAttributeMaxDynamicSharedMemorySize, GEMM_SMEM);

    // CSR + el/er buffer zero + W-prep
    zero_kernel <<<(3 * N_NODES + 255) / 256, 256>>>();
    count_kernel<<<(N_EDGES + 255) / 256, 256>>>(dst);
    scan_kernel <<<1, 1024>>>();
    prep_kernel <<<PREP_B, 256>>>(src, dst,
                                  W[0], W[1], W[2], W[3],
                                  al[0], al[1], al[2], al[3],
                                  ar[0], ar[1], ar[2], ar[3]);

    const int din_a [4] = {64, 128, 256, 512};
    const int dout_a[4] = {128, 256, 512, 1024};
    // chunks per node: din=64 -> 1 (VEC=2, 64ch/warp); din>=128 -> din/128 (VEC=4)
    const int l2c_a [4] = {0, 0, 1, 2};
    const int wpoff [4] = {0, 4, 20, 84};

    // el/er for layer 0 from feat
    elr_kernel<<<(N_NODES * 32 + 255) / 256, 256>>>(feat, 64, 0);

    const float* x = feat;
    float* outbufs[4] = {pA, pB, pA, pB};

    for (int l = 0; l < 4; l++) {
        int din = din_a[l], dout = dout_a[l];
        int mrows = (l == 3) ? N_OUT : N_NODES;

        int warps = mrows << l2c_a[l];
        int blocks = (warps * 32 + 255) / 256;
        const float* elC = pEl + (size_t)l * N_NODES;
        const float* erC = pEr + (size_t)l * N_NODES;
        if (l == 0)
            gather_kernel<2><<<blocks, 256>>>(x, pZ, elC, erC, din, l2c_a[l], mrows);
        else
            gather_kernel<4><<<blocks, 256>>>(x, pZ, elC, erC, din, l2c_a[l], mrows);

        const float* walN = nullptr;
        const float* warN = nullptr;
        float* elN = nullptr;
        float* erN = nullptr;
        if (l < 3) {
            walN = pWal + (size_t)(l + 1) * 512;
            warN = pWar + (size_t)(l + 1) * 512;
            elN  = pEl + (size_t)(l + 1) * N_NODES;
            erN  = pEr + (size_t)(l + 1) * N_NODES;
        }

        float* y = outbufs[l];
        dim3 grid(dout / GBN, (mrows + GBM - 1) / GBM);
        gemm_tf32_kernel<<<grid, 256, GEMM_SMEM>>>(
            pZ, pWp + (size_t)wpoff[l] * B_TILE_F, bb[l], y,
            walN, warN, elN, erN, mrows, din, dout);

        x = y;
    }

    dim3 pg(MAXD / 256, 32);
    pool_kernel<<<pg, 256>>>(pB, order);
    logits_kernel<<<1, 64>>>(relW, relB, rel, order, out);
}